// round 4
// baseline (speedup 1.0000x reference)
#include <cuda_runtime.h>

#define BB 16
#define CC 64
#define HH 192
#define WW 192
#define HT 64   // pooled spatial size

// scratch (static device globals -- no runtime allocation allowed)
__device__ float g_xtem[BB*CC*HT*HT];
__device__ float g_gate[BB*CC*HT*HT];

// -------------------------------------------------------------------------
// Kernel 1: fused maxpool3x3(s1,p1) + blurpool(4x4, s3, reflect(1,2)),
// separable form: vmax -> hmax (in place) -> vblur -> hblur.
// One block = 8 output rows x 64 cols of one (b,c) plane. grid (8, 1024).
// -------------------------------------------------------------------------
__global__ void k_pool(const float* __restrict__ x) {
    __shared__ float vm[25][192];  // vmax, then 3x3-max (in place)
    __shared__ float cb[8][192];   // vertically blurred rows
    int plane  = blockIdx.y;
    int oh0    = blockIdx.x * 8;
    int prbase = 3*oh0 - 1;        // pr corresponding to vm row 0
    const float* xp = x + (size_t)plane * (HH*WW);
    int tid = threadIdx.x;

    // stage 1: vm[rr][c] = max over x rows (pr-1..pr+1, clamped), float4
    for (int i = tid; i < 25*48; i += 256) {
        int rr = i / 48, q = i % 48;
        int pr = prbase + rr;
        int ra = min(max(pr-1, 0), 191);
        int rb = min(max(pr,   0), 191);
        int rc = min(max(pr+1, 0), 191);
        float4 a = __ldg((const float4*)(xp + (size_t)ra*WW) + q);
        float4 b = __ldg((const float4*)(xp + (size_t)rb*WW) + q);
        float4 c = __ldg((const float4*)(xp + (size_t)rc*WW) + q);
        float4 m;
        m.x = fmaxf(fmaxf(a.x, b.x), c.x);
        m.y = fmaxf(fmaxf(a.y, b.y), c.y);
        m.z = fmaxf(fmaxf(a.z, b.z), c.z);
        m.w = fmaxf(fmaxf(a.w, b.w), c.w);
        *((float4*)&vm[rr][0] + q) = m;
    }
    __syncthreads();

    // stage 2: in-place horizontal 3-max (clamped) via register staging
    float4 res[5];
    int cnt = 0;
    for (int i = tid; i < 25*48; i += 256) {
        int rr = i / 48, q = i % 48;
        float4 v = *((float4*)&vm[rr][0] + q);
        float left  = vm[rr][max(q*4 - 1, 0)];
        float right = vm[rr][min(q*4 + 4, 191)];
        float4 m;
        m.x = fmaxf(fmaxf(left, v.x), v.y);
        m.y = fmaxf(fmaxf(v.x,  v.y), v.z);
        m.z = fmaxf(fmaxf(v.y,  v.z), v.w);
        m.w = fmaxf(fmaxf(v.z,  v.w), right);
        res[cnt++] = m;
    }
    __syncthreads();
    cnt = 0;
    for (int i = tid; i < 25*48; i += 256) {
        int rr = i / 48, q = i % 48;
        *((float4*)&vm[rr][0] + q) = res[cnt++];
    }
    __syncthreads();

    // stage 3: vertical blur (1,3,3,1), taps at vm rows 3*ohl+u; reflect pr=-1 -> 1
    for (int i = tid; i < 8*48; i += 256) {
        int ohl = i / 48, q = i % 48;
        int oh = oh0 + ohl;
        int rbase = 3*ohl;
        int r0i = (oh == 0) ? 2 : rbase;   // pr=-1 reflects to pr=1 (vm row 2)
        float4 t0 = *((float4*)&vm[r0i    ][0] + q);
        float4 t1 = *((float4*)&vm[rbase+1][0] + q);
        float4 t2 = *((float4*)&vm[rbase+2][0] + q);
        float4 t3 = *((float4*)&vm[rbase+3][0] + q);
        float4 o;
        o.x = t0.x + 3.f*t1.x + 3.f*t2.x + t3.x;
        o.y = t0.y + 3.f*t1.y + 3.f*t2.y + t3.y;
        o.z = t0.z + 3.f*t1.z + 3.f*t2.z + t3.z;
        o.w = t0.w + 3.f*t1.w + 3.f*t2.w + t3.w;
        *((float4*)&cb[ohl][0] + q) = o;
    }
    __syncthreads();

    // stage 4: horizontal blur (1,3,3,1) at cols 3*ow-1+v; reflect pc=-1 -> 1
    for (int i = tid; i < 512; i += 256) {
        int ohl = i >> 6, ow = i & 63;
        int cbase = 3*ow - 1;
        float s = cb[ohl][(cbase < 0) ? 1 : cbase]
                + 3.f*cb[ohl][cbase+1]
                + 3.f*cb[ohl][cbase+2]
                +      cb[ohl][cbase+3];
        g_xtem[(size_t)plane*(HT*HT) + (oh0+ohl)*HT + ow] = s * (1.f/64.f);
    }
}

// -------------------------------------------------------------------------
// Kernel 2: combined 4x depthwise-conv (87-tap sparse 13x13 stencil) + BN +
// sigmoid. One block per (b,c) plane; per-channel stencil built in smem.
// -------------------------------------------------------------------------
__global__ void k_att(const float* __restrict__ wh1, const float* __restrict__ wv1,
                      const float* __restrict__ wh2, const float* __restrict__ wv2,
                      const float* __restrict__ gamma, const float* __restrict__ beta,
                      const float* __restrict__ mean,  const float* __restrict__ var) {
    __shared__ float tile[76*80];   // 64x64 plane, halo 6, row stride 80, col off 8
    __shared__ float wc[169];       // combined 13x13 stencil for this channel
    int plane = blockIdx.x;
    int ch    = plane % CC;
    int tid   = threadIdx.x;

    float4 z4 = make_float4(0.f,0.f,0.f,0.f);
    for (int i = tid; i < (76*80)/4; i += 256) ((float4*)tile)[i] = z4;
    if (tid < 169) wc[tid] = 0.f;
    __syncthreads();
    if (tid < 33) { int a = tid/3  - 5, b = tid%3  - 1; wc[(a+6)*13 + (b+6)]     += wh1[ch*33 + tid]; }
    __syncthreads();
    if (tid < 33) { int a = tid/11 - 1, b = tid%11 - 5; wc[(a+6)*13 + (b+6)]     += wv1[ch*33 + tid]; }
    __syncthreads();
    if (tid < 33) { int a = tid/3  - 5, b = tid%3  - 1; wc[(a+6)*13 + (b-a+6)]   += wh2[ch*33 + tid]; }
    __syncthreads();
    if (tid < 33) { int s = tid/11 - 1, t = tid%11 - 5; wc[(s-t+6)*13 + (t+6)]   += wv2[ch*33 + tid]; }

    const float4* src = (const float4*)(g_xtem + (size_t)plane*(HT*HT));
    for (int i = tid; i < 1024; i += 256) {
        int r = i / 16, c4 = i % 16;
        *((float4*)&tile[(r+6)*80 + c4*4 + 8]) = src[i];
    }
    __syncthreads();

    int lane = tid & 31, w = tid >> 5;
    int c  = (w & 1)*32 + lane;     // output column
    int r0 = (w >> 1)*16;           // first of 16 output rows
    float acc[16];
    #pragma unroll
    for (int k = 0; k < 16; k++) acc[k] = 0.f;

    constexpr int LO[13] = {5,-1,-1,-1,-1,-5,-5,-5,-3,-4,-5,-6,-5};
    constexpr int HI[13] = {5, 6, 5, 4, 3, 5, 5, 5, 1, 1, 1, 1,-5};
    #pragma unroll
    for (int d = 0; d < 13; d++) {
        int cidx = c + d + 2;
        float xr[28];
        #pragma unroll
        for (int m = LO[d]+6; m <= HI[d]+21; m++)
            xr[m] = tile[(r0 + m)*80 + cidx];
        #pragma unroll
        for (int di = LO[d]; di <= HI[d]; di++) {
            float wv = wc[(di+6)*13 + d];
            #pragma unroll
            for (int k = 0; k < 16; k++)
                acc[k] += wv * xr[k + di + 6];
        }
    }

    float inv = gamma[ch] * rsqrtf(var[ch] + 1e-5f);
    float b2  = beta[ch] - mean[ch]*inv;
    float* gp = g_gate + (size_t)plane*(HT*HT);
    #pragma unroll
    for (int k = 0; k < 16; k++) {
        float a = acc[k]*inv + b2;
        gp[(r0 + k)*HT + c] = 1.f / (1.f + __expf(-a));
    }
}

// -------------------------------------------------------------------------
// Kernel 3: out = x * gate[i/3, j/3]; one thread = 12 consecutive cols
// (3 float4s, 4 gate values). grid 12288 x 256.
// -------------------------------------------------------------------------
__global__ void k_mul(const float* __restrict__ x, float* __restrict__ out) {
    int t   = blockIdx.x*256 + threadIdx.x;
    int seg = t & 15;            // 16 segments of 12 cols per row
    int r   = t >> 4;            // global row = plane*192 + i
    int i   = r % 192;
    int p   = r / 192;
    const float* grow = g_gate + (size_t)p*(HT*HT) + (i/3)*HT;
    int gq = seg*4;
    float g0 = grow[gq+0], g1 = grow[gq+1], g2 = grow[gq+2], g3 = grow[gq+3];
    const float4* xr = (const float4*)(x + (size_t)r*WW) + seg*3;
    float4* orow     = (float4*)(out + (size_t)r*WW) + seg*3;
    float4 a = xr[0], b = xr[1], c = xr[2];
    float4 oa, ob, oc;
    oa.x = a.x*g0; oa.y = a.y*g0; oa.z = a.z*g0; oa.w = a.w*g1;
    ob.x = b.x*g1; ob.y = b.y*g1; ob.z = b.z*g2; ob.w = b.w*g2;
    oc.x = c.x*g2; oc.y = c.y*g3; oc.z = c.z*g3; oc.w = c.w*g3;
    orow[0] = oa; orow[1] = ob; orow[2] = oc;
}

extern "C" void kernel_launch(void* const* d_in, const int* in_sizes, int n_in,
                              void* d_out, int out_size) {
    const float* x     = (const float*)d_in[0];
    const float* wh1   = (const float*)d_in[1];
    const float* wv1   = (const float*)d_in[2];
    const float* wh2   = (const float*)d_in[3];
    const float* wv2   = (const float*)d_in[4];
    const float* gamma = (const float*)d_in[5];
    const float* beta  = (const float*)d_in[6];
    const float* mean  = (const float*)d_in[7];
    const float* var   = (const float*)d_in[8];
    float* out = (float*)d_out;

    k_pool<<<dim3(8, BB*CC), 256>>>(x);
    k_att<<<BB*CC, 256>>>(wh1, wv1, wh2, wv2, gamma, beta, mean, var);
    k_mul<<<12288, 256>>>(x, out);
}

// round 5
// speedup vs baseline: 1.4064x; 1.4064x over previous
#include <cuda_runtime.h>

#define BB 16
#define CC 64
#define HH 192
#define WW 192
#define HT 64   // pooled spatial size

// scratch (static device global -- no runtime allocation allowed)
__device__ float g_xtem[BB*CC*HT*HT];

// -------------------------------------------------------------------------
// Kernel 1: fused maxpool3x3(s1,p1) + blurpool(4x4, s3, reflect(1,2)),
// separable: vmax -> hmax -> vblur -> hblur.
// Block = (48,5) = 240 threads, 8 output rows x 64 cols of one plane.
// q = threadIdx.x is the fixed column-quad -> no div/mod in hot loops.
// -------------------------------------------------------------------------
__global__ void k_pool(const float* __restrict__ x) {
    __shared__ float vm[25][192];  // vertical 3-max
    __shared__ float hm[25][192];  // 3x3 max
    __shared__ float cb[8][192];   // vertically blurred rows
    int plane  = blockIdx.y;
    int oh0    = blockIdx.x * 8;
    int prbase = 3*oh0 - 1;        // pr of vm row 0
    const float* xp = x + (size_t)plane * (HH*WW);
    int q  = threadIdx.x;          // 0..47 (column quad)
    int ry = threadIdx.y;          // 0..4

    // stage 1: vm[rr][4q..4q+3] = max over input rows pr-1..pr+1 (clamped)
    #pragma unroll
    for (int k = 0; k < 5; k++) {
        int rr = ry*5 + k;
        int pr = prbase + rr;
        int ra = min(max(pr-1, 0), 191);
        int rb = min(max(pr,   0), 191);
        int rc = min(max(pr+1, 0), 191);
        float4 a = __ldg((const float4*)(xp + (size_t)ra*WW) + q);
        float4 b = __ldg((const float4*)(xp + (size_t)rb*WW) + q);
        float4 c = __ldg((const float4*)(xp + (size_t)rc*WW) + q);
        float4 m;
        m.x = fmaxf(fmaxf(a.x, b.x), c.x);
        m.y = fmaxf(fmaxf(a.y, b.y), c.y);
        m.z = fmaxf(fmaxf(a.z, b.z), c.z);
        m.w = fmaxf(fmaxf(a.w, b.w), c.w);
        *((float4*)&vm[rr][0] + q) = m;
    }
    __syncthreads();

    // stage 2: horizontal 3-max (clamped)
    #pragma unroll
    for (int k = 0; k < 5; k++) {
        int rr = ry*5 + k;
        float4 v = *((float4*)&vm[rr][0] + q);
        float left  = vm[rr][max(4*q - 1, 0)];
        float right = vm[rr][min(4*q + 4, 191)];
        float4 m;
        m.x = fmaxf(fmaxf(left, v.x), v.y);
        m.y = fmaxf(fmaxf(v.x,  v.y), v.z);
        m.z = fmaxf(fmaxf(v.y,  v.z), v.w);
        m.w = fmaxf(fmaxf(v.z,  v.w), right);
        *((float4*)&hm[rr][0] + q) = m;
    }
    __syncthreads();

    // stage 3: vertical blur (1,3,3,1): taps hm rows 3*ohl+u; reflect pr=-1 -> 1
    #pragma unroll
    for (int k = 0; k < 2; k++) {
        int ohl = ry + k*5;
        if (ohl < 8) {
            int rbase = 3*ohl;
            int r0i = (oh0 + ohl == 0) ? 2 : rbase;  // reflect
            float4 t0 = *((float4*)&hm[r0i    ][0] + q);
            float4 t1 = *((float4*)&hm[rbase+1][0] + q);
            float4 t2 = *((float4*)&hm[rbase+2][0] + q);
            float4 t3 = *((float4*)&hm[rbase+3][0] + q);
            float4 o;
            o.x = t0.x + 3.f*t1.x + 3.f*t2.x + t3.x;
            o.y = t0.y + 3.f*t1.y + 3.f*t2.y + t3.y;
            o.z = t0.z + 3.f*t1.z + 3.f*t2.z + t3.z;
            o.w = t0.w + 3.f*t1.w + 3.f*t2.w + t3.w;
            *((float4*)&cb[ohl][0] + q) = o;
        }
    }
    __syncthreads();

    // stage 4: horizontal blur at cols 3*ow-1+v; reflect pc=-1 -> 1
    int tid = ry*48 + q;
    for (int i = tid; i < 512; i += 240) {
        int ohl = i >> 6, ow = i & 63;
        int cbase = 3*ow - 1;
        float s = cb[ohl][(cbase < 0) ? 1 : cbase]
                + 3.f*cb[ohl][cbase+1]
                + 3.f*cb[ohl][cbase+2]
                +      cb[ohl][cbase+3];
        g_xtem[(size_t)plane*(HT*HT) + (oh0+ohl)*HT + ow] = s * (1.f/64.f);
    }
}

// -------------------------------------------------------------------------
// Kernel 2 (fused): combined 87-tap stencil + BN + sigmoid -> gate in smem,
// then streamed out = x * gate[i/3, j/3] for the whole plane (coalesced).
// One block per (b,c) plane, 256 threads.
// -------------------------------------------------------------------------
__global__ void k_att(const float* __restrict__ wh1, const float* __restrict__ wv1,
                      const float* __restrict__ wh2, const float* __restrict__ wv2,
                      const float* __restrict__ gamma, const float* __restrict__ beta,
                      const float* __restrict__ mean,  const float* __restrict__ var,
                      const float* __restrict__ x,     float* __restrict__ out) {
    __shared__ float tile[76*80];   // 64x64 plane, halo 6, row stride 80, col off 8
    __shared__ float wc[169];       // combined 13x13 stencil
    __shared__ float gs[64*64];     // gate
    int plane = blockIdx.x;
    int ch    = plane % CC;
    int tid   = threadIdx.x;

    float4 z4 = make_float4(0.f,0.f,0.f,0.f);
    for (int i = tid; i < (76*80)/4; i += 256) ((float4*)tile)[i] = z4;
    if (tid < 169) wc[tid] = 0.f;
    __syncthreads();
    if (tid < 33) { int a = tid/3  - 5, b = tid%3  - 1; wc[(a+6)*13 + (b+6)]   += wh1[ch*33 + tid]; }
    __syncthreads();
    if (tid < 33) { int a = tid/11 - 1, b = tid%11 - 5; wc[(a+6)*13 + (b+6)]   += wv1[ch*33 + tid]; }
    __syncthreads();
    if (tid < 33) { int a = tid/3  - 5, b = tid%3  - 1; wc[(a+6)*13 + (b-a+6)] += wh2[ch*33 + tid]; }
    __syncthreads();
    if (tid < 33) { int s = tid/11 - 1, t = tid%11 - 5; wc[(s-t+6)*13 + (t+6)] += wv2[ch*33 + tid]; }

    const float4* src = (const float4*)(g_xtem + (size_t)plane*(HT*HT));
    for (int i = tid; i < 1024; i += 256) {
        int r = i / 16, c4 = i % 16;
        *((float4*)&tile[(r+6)*80 + c4*4 + 8]) = src[i];
    }
    __syncthreads();

    // ---- phase A: stencil + BN + sigmoid -> gs ----
    {
        int lane = tid & 31, w = tid >> 5;
        int c  = (w & 1)*32 + lane;
        int r0 = (w >> 1)*16;
        float acc[16];
        #pragma unroll
        for (int k = 0; k < 16; k++) acc[k] = 0.f;

        constexpr int LO[13] = {5,-1,-1,-1,-1,-5,-5,-5,-3,-4,-5,-6,-5};
        constexpr int HI[13] = {5, 6, 5, 4, 3, 5, 5, 5, 1, 1, 1, 1,-5};
        #pragma unroll
        for (int d = 0; d < 13; d++) {
            int cidx = c + d + 2;
            float xr[28];
            #pragma unroll
            for (int m = LO[d]+6; m <= HI[d]+21; m++)
                xr[m] = tile[(r0 + m)*80 + cidx];
            #pragma unroll
            for (int di = LO[d]; di <= HI[d]; di++) {
                float wv = wc[(di+6)*13 + d];
                #pragma unroll
                for (int k = 0; k < 16; k++)
                    acc[k] += wv * xr[k + di + 6];
            }
        }

        float inv = gamma[ch] * rsqrtf(var[ch] + 1e-5f);
        float b2  = beta[ch] - mean[ch]*inv;
        #pragma unroll
        for (int k = 0; k < 16; k++) {
            float a = acc[k]*inv + b2;
            gs[(r0 + k)*64 + c] = 1.f / (1.f + __expf(-a));
        }
    }
    __syncthreads();

    // ---- phase B: out = x * gate (3x nearest upsample), coalesced float4 ----
    const float4* xp4 = (const float4*)(x   + (size_t)plane*(HH*WW));
    float4*       op4 = (float4*)     (out + (size_t)plane*(HH*WW));
    #pragma unroll 4
    for (int it = 0; it < 36; ++it) {
        int i    = it*256 + tid;        // float4 index within plane (0..9215)
        int rowi = i / 48;
        int j    = i - rowi*48;         // float4 col
        int gr   = rowi / 3;            // gate row
        int q3   = j / 3;
        int rem  = j - 3*q3;
        const float* grow = gs + gr*64;
        float lo = grow[4*q3 + rem];
        float hi = grow[4*q3 + rem + 1];
        float4 a = xp4[i];
        float4 o;
        o.x = a.x * lo;
        o.y = a.y * ((rem == 2) ? hi : lo);
        o.z = a.z * ((rem >= 1) ? hi : lo);
        o.w = a.w * hi;
        op4[i] = o;
    }
}

extern "C" void kernel_launch(void* const* d_in, const int* in_sizes, int n_in,
                              void* d_out, int out_size) {
    const float* x     = (const float*)d_in[0];
    const float* wh1   = (const float*)d_in[1];
    const float* wv1   = (const float*)d_in[2];
    const float* wh2   = (const float*)d_in[3];
    const float* wv2   = (const float*)d_in[4];
    const float* gamma = (const float*)d_in[5];
    const float* beta  = (const float*)d_in[6];
    const float* mean  = (const float*)d_in[7];
    const float* var   = (const float*)d_in[8];
    float* out = (float*)d_out;

    k_pool<<<dim3(8, BB*CC), dim3(48, 5)>>>(x);
    k_att<<<BB*CC, 256>>>(wh1, wv1, wh2, wv2, gamma, beta, mean, var, x, out);
}